// round 9
// baseline (speedup 1.0000x reference)
#include <cuda_runtime.h>

#define NV 576
#define MROWS 144
#define ROW_DEG 15
#define BATCH 256
#define ITERS 3
#define THREADS (4 * MROWS)        // 576: four threads per check row
#define MAXD 16                    // padded max column degree (slot range)
#define CSTRIDE 20                 // E_cm column stride in floats (80B) -> conflict-free LDS.128
#define FBIG 3.4e38f

// Packed per-edge descriptor: (E_cm offset << 16) | column. Row-padded to 16
// entries (64B); each quarter-row thread loads its 4 with 1x LDG.128.
__device__ int g_edge[MROWS * 16];
// Monotone per-column counters for slot assignment. Never reset: (s + c) & 15
// stays distinct within a column for any base as long as degree <= 16.
__device__ unsigned g_cnt[NV];

// One CTA per check row, one thread per column: single parallel LDG round,
// ballot + cross-warp prefix -> edge position (columns ascending, matching
// top_k's lowest-index tie-break), then a global atomic gives the column slot.
__global__ __launch_bounds__(NV) void prep_kernel(const float* __restrict__ H) {
    __shared__ int wcnt[NV / 32];
    const int m = blockIdx.x;
    const int t = threadIdx.x;
    const int lane = t & 31;
    const int w = t >> 5;

    float v = H[m * NV + t];
    unsigned ball = __ballot_sync(0xffffffffu, v != 0.0f);
    if (lane == 0) wcnt[w] = __popc(ball);
    __syncthreads();

    int pre = __popc(ball & ((1u << lane) - 1u));
    #pragma unroll
    for (int k = 0; k < NV / 32; ++k)
        pre += (k < w) ? wcnt[k] : 0;

    if (v != 0.0f) {
        unsigned s = atomicAdd(&g_cnt[t], 1u);
        int se = (int)((s + (unsigned)t) & (MAXD - 1u));
        int off = t * CSTRIDE + se;              // < 11520, fits in 16 bits
        g_edge[m * 16 + pre] = (off << 16) | t;
    }
}

__global__ __launch_bounds__(THREADS, 2) void ldpc_kernel(
    const float* __restrict__ r,
    const float* __restrict__ alpha,
    const float* __restrict__ beta,
    float* __restrict__ out)
{
    extern __shared__ float sm[];
    float* r_s  = sm;                     // [NV]
    float* sE   = sm + NV;                // [2][NV] ping-pong: r + col sums of E
    float* E_cm = sm + 3 * NV;            // [NV*CSTRIDE] column-major padded E

    const int tid  = threadIdx.x;
    const int row  = tid >> 2;
    const int part = tid & 3;             // edges [4p, 4p+3] (part 3: 3 live + dummy)
    const int b    = blockIdx.x;
    const int nloc = (part == 3) ? 3 : 4;
    const int jgb  = part * 4;

    // ---- prefetch global loads (overlap DRAM latency with init STS) ----
    const int4 e0 = *(const int4*)(g_edge + row * 16 + part * 4);
    const float rv = r[b * NV + tid];     // one column per thread

    float alv[ITERS], bev[ITERS];
    #pragma unroll
    for (int k = 0; k < ITERS; ++k) { alv[k] = alpha[k]; bev[k] = beta[k]; }

    // Zero E_cm once (pads stay 0; live slots rewritten each iteration)
    float4* ez = (float4*)E_cm;
    #pragma unroll
    for (int i = tid; i < NV * CSTRIDE / 4; i += THREADS)
        ez[i] = make_float4(0.f, 0.f, 0.f, 0.f);

    r_s[tid] = rv;
    sE[tid]  = rv;

    int cc[4], sl[4];
    {
        int e[4] = { e0.x, e0.y, e0.z, e0.w };
        #pragma unroll
        for (int j = 0; j < 4; ++j) {
            cc[j] = e[j] & 0xFFFF;
            sl[j] = ((unsigned)e[j]) >> 16;
        }
    }

    float Ev[4] = {0.f, 0.f, 0.f, 0.f};

    __syncthreads();

    int cur = 0;

    #pragma unroll
    for (int it = 0; it < ITERS; ++it) {
        // ── check-node phase: each thread scans its <=4 edges ──
        float Mv[4];
        const float* sEc = sE + cur * NV;
        #pragma unroll
        for (int j = 0; j < 4; ++j)
            Mv[j] = sEc[cc[j]] - Ev[j];          // r + sumE - E_j
        if (part == 3) Mv[3] = FBIG;             // dummy: +big, sign 0, never min

        // local sign parity (dummy positive -> no contribution)
        unsigned px = (__float_as_uint(Mv[0]) ^ __float_as_uint(Mv[1]))
                    ^ (__float_as_uint(Mv[2]) ^ __float_as_uint(Mv[3]));

        // local min1 + argmin + min2 over 4
        float f0 = fabsf(Mv[0]), f1 = fabsf(Mv[1]);
        float f2 = fabsf(Mv[2]), f3 = fabsf(Mv[3]);
        float m1l = fminf(fminf(f0, f1), fminf(f2, f3));
        unsigned msk = ((f0 == m1l) ? 1u : 0u) | ((f1 == m1l) ? 2u : 0u)
                     | ((f2 == m1l) ? 4u : 0u) | ((f3 == m1l) ? 8u : 0u);
        const int j1l = __ffs(msk) - 1;
        float t0 = (j1l == 0) ? FBIG : f0, t1 = (j1l == 1) ? FBIG : f1;
        float t2 = (j1l == 2) ? FBIG : f2, t3 = (j1l == 3) ? FBIG : f3;
        float m2l = fminf(fminf(t0, t1), fminf(t2, t3));

        float M1 = m1l, M2 = m2l;
        int   J1 = j1l + jgb;

        // ── 2-level tournament merge across the 4 lanes of this row ──
        #pragma unroll
        for (int d = 1; d <= 2; d <<= 1) {
            float m1o = __shfl_xor_sync(0xffffffffu, M1, d);
            float m2o = __shfl_xor_sync(0xffffffffu, M2, d);
            int   j1o = __shfl_xor_sync(0xffffffffu, J1, d);
            unsigned pxo = __shfl_xor_sync(0xffffffffu, px, d);
            px ^= pxo;
            bool ow = (m1o < M1) || (m1o == M1 && j1o < J1);
            M2 = fminf(fminf(M2, m2o), ow ? M1 : m1o);
            M1 = ow ? m1o : M1;
            J1 = ow ? j1o : J1;
        }
        px &= 0x80000000u;

        // sign(0)=0 kills the whole row  <=>  M1 == 0
        const float zal = (M1 == 0.0f) ? 0.0f : alv[it];
        const float m1c = fmaxf(0.0f, M1 - bev[it]) * zal;
        const float m2c = fmaxf(0.0f, M2 - bev[it]) * zal;

        #pragma unroll
        for (int j = 0; j < 4; ++j) {
            float mag = ((j + jgb) == J1) ? m2c : m1c;
            unsigned sb = (px ^ __float_as_uint(Mv[j])) & 0x80000000u;
            float Ej = __uint_as_float(__float_as_uint(mag) ^ sb);
            Ev[j] = Ej;
            if (j < nloc) E_cm[sl[j]] = Ej;      // skip dummy store
        }
        __syncthreads();

        // ── variable-node phase: 1 column per thread, 4x LDS.128, conflict-free ──
        const int nxt = cur ^ 1;
        {
            const int c = tid;
            const float4* p = (const float4*)(E_cm + c * CSTRIDE);
            float4 x = p[0], y = p[1], u = p[2], w = p[3];
            float ssum = ((x.x + x.y) + (x.z + x.w)) + ((y.x + y.y) + (y.z + y.w))
                       + ((u.x + u.y) + (u.z + u.w)) + ((w.x + w.y) + (w.z + w.w));
            float cs = rv + ssum;
            if (it == ITERS - 1)
                out[b * NV + c] = cs;
            else
                sE[nxt * NV + c] = cs;
        }
        if (it != ITERS - 1) __syncthreads();
        cur = nxt;
    }
}

extern "C" void kernel_launch(void* const* d_in, const int* in_sizes, int n_in,
                              void* d_out, int out_size)
{
    const float* r     = (const float*)d_in[0];   // [256, 576]
    const float* H     = (const float*)d_in[1];   // [144, 576]
    const float* alpha = (const float*)d_in[2];   // [3]
    const float* beta  = (const float*)d_in[3];   // [3]
    float* out = (float*)d_out;                   // [256, 576]

    const int smem = (3 * NV + NV * CSTRIDE) * sizeof(float);  // ~53 KB -> 2 CTAs/SM
    cudaFuncSetAttribute(ldpc_kernel, cudaFuncAttributeMaxDynamicSharedMemorySize, smem);

    prep_kernel<<<MROWS, NV>>>(H);
    ldpc_kernel<<<BATCH, THREADS, smem>>>(r, alpha, beta, out);
}